// round 1
// baseline (speedup 1.0000x reference)
#include <cuda_runtime.h>
#include <cuda_bf16.h>
#include <math.h>

// Problem constants
#define Bq 2
#define Sq 2048
#define Dq 768
#define Hq 12
#define Vq 50257
#define Fq 3072
#define HDq 64
#define Mq (Bq * Sq)   // 4096 rows

// ---------------- scratch (static device memory; no allocation at runtime) ---
__device__ float g_x   [Mq * Dq];        // emb + pos
__device__ float g_qkv [Mq * 3 * Dq];    // qkv
__device__ float g_attn[Mq * Dq];        // attention output
__device__ float g_mha [Mq * Dq];        // proj + residual
__device__ float g_h1  [Mq * Dq];        // LN1 out
__device__ float g_ff  [Mq * Fq];        // relu(h1 W1 + b1)
__device__ float g_res2[Mq * Dq];        // ff W2 + b2 + h1
__device__ float g_h2  [Mq * Dq];        // LN2 out
__device__ float g_weff[Dq * Dq];        // sum_h W_o[h*768+m, n]

// ---------------- embedding + positional encoding ----------------------------
__global__ void embed_pos_kernel(const int* __restrict__ inp,
                                 const float* __restrict__ emb,
                                 float* __restrict__ x) {
    int row = blockIdx.x;              // 0..4095 = b*S + s
    int s = row % Sq;
    int tok = inp[row];
    const float* e = emb + (size_t)tok * Dq;
    float* xr = x + (size_t)row * Dq;
    for (int d = threadIdx.x; d < Dq; d += blockDim.x) {
        float ex = 2.0f * (float)d / (float)Dq;
        float denom = powf(10000.0f, ex);
        float val = (float)s / denom;
        float pe = (d & 1) ? cosf(val) : sinf(val);
        xr[d] = e[d] + pe;
    }
}

// ---------------- W_eff = sum over heads of W_o blocks -----------------------
__global__ void weff_kernel(const float* __restrict__ W_o, float* __restrict__ W_eff) {
    int idx = blockIdx.x * blockDim.x + threadIdx.x;
    if (idx >= Dq * Dq) return;
    int m = idx / Dq, n = idx % Dq;
    float s = 0.f;
    #pragma unroll
    for (int h = 0; h < Hq; h++)
        s += W_o[((size_t)h * Dq + m) * Dq + n];
    W_eff[idx] = s;
}

// ---------------- generic tiled SGEMM: C = A[MxK] B[KxN] (+bias)(+res)(relu) -
// BM=BN=128, BK=8, 256 threads, 8x8 per thread.
__global__ void __launch_bounds__(256)
sgemm_kernel(const float* __restrict__ A, const float* __restrict__ B,
             const float* __restrict__ bias, const float* __restrict__ res,
             float* __restrict__ C, int M, int N, int K, int relu) {
    const int BM = 128, BN = 128, BK = 8;
    __shared__ float As[BK][BM];
    __shared__ float Bs[BK][BN + 4];

    int tid = threadIdx.x;
    int tx = tid & 15, ty = tid >> 4;
    int m0 = blockIdx.y * BM, n0 = blockIdx.x * BN;

    int aRow = tid >> 1, aCol = (tid & 1) * 4;   // 128 rows x 8 cols of A
    int bRow = tid >> 5, bCol = (tid & 31) * 4;  // 8 rows x 128 cols of B

    float acc[8][8];
    #pragma unroll
    for (int i = 0; i < 8; i++)
        #pragma unroll
        for (int j = 0; j < 8; j++) acc[i][j] = 0.f;

    bool fastB = ((N & 3) == 0) && (n0 + BN <= N);

    for (int k0 = 0; k0 < K; k0 += BK) {
        // load A tile (transposed into smem)
        float4 av = *(const float4*)(A + (size_t)(m0 + aRow) * K + k0 + aCol);
        As[aCol + 0][aRow] = av.x;
        As[aCol + 1][aRow] = av.y;
        As[aCol + 2][aRow] = av.z;
        As[aCol + 3][aRow] = av.w;
        // load B tile
        const float* Bp = B + (size_t)(k0 + bRow) * N + n0 + bCol;
        if (fastB) {
            float4 bv = *(const float4*)Bp;
            Bs[bRow][bCol + 0] = bv.x;
            Bs[bRow][bCol + 1] = bv.y;
            Bs[bRow][bCol + 2] = bv.z;
            Bs[bRow][bCol + 3] = bv.w;
        } else {
            #pragma unroll
            for (int i = 0; i < 4; i++) {
                int n = n0 + bCol + i;
                Bs[bRow][bCol + i] = (n < N) ? Bp[i] : 0.f;
            }
        }
        __syncthreads();

        #pragma unroll
        for (int kk = 0; kk < BK; kk++) {
            float a[8], b[8];
            #pragma unroll
            for (int i = 0; i < 8; i++) a[i] = As[kk][ty * 8 + i];
            #pragma unroll
            for (int j = 0; j < 8; j++) b[j] = Bs[kk][tx * 8 + j];
            #pragma unroll
            for (int i = 0; i < 8; i++)
                #pragma unroll
                for (int j = 0; j < 8; j++)
                    acc[i][j] = fmaf(a[i], b[j], acc[i][j]);
        }
        __syncthreads();
    }

    // epilogue
    #pragma unroll
    for (int i = 0; i < 8; i++) {
        int m = m0 + ty * 8 + i;
        #pragma unroll
        for (int j = 0; j < 8; j++) {
            int n = n0 + tx * 8 + j;
            if (n < N) {
                float v = acc[i][j];
                if (bias) v += bias[n];
                if (res)  v += res[(size_t)m * N + n];
                if (relu) v = fmaxf(v, 0.f);
                C[(size_t)m * N + n] = v;
            }
        }
    }
}

// ---------------- flash attention (causal, HD=64) -----------------------------
// grid: (S/64, B*H), block: 64 threads; each thread owns one query row.
__global__ void __launch_bounds__(64)
attn_kernel(const float* __restrict__ qkv, float* __restrict__ out) {
    int qt = blockIdx.x;
    int bh = blockIdx.y;
    int b = bh / Hq, h = bh % Hq;
    int tid = threadIdx.x;
    int qrow = qt * 64 + tid;

    const float* base = qkv + (size_t)b * Sq * 3 * Dq;

    float qreg[64];
    {
        const float* qp = base + (size_t)qrow * 3 * Dq + h * HDq;
        #pragma unroll
        for (int d4 = 0; d4 < 16; d4++) {
            float4 v = ((const float4*)qp)[d4];
            qreg[d4 * 4 + 0] = v.x; qreg[d4 * 4 + 1] = v.y;
            qreg[d4 * 4 + 2] = v.z; qreg[d4 * 4 + 3] = v.w;
        }
    }

    float acc[64];
    #pragma unroll
    for (int d = 0; d < 64; d++) acc[d] = 0.f;
    float m = -INFINITY, l = 0.f;

    __shared__ float Ks[64][65];
    __shared__ float Vs[64][65];

    for (int kt = 0; kt <= qt; kt++) {
        const float* kp = base + (size_t)(kt * 64 + tid) * 3 * Dq + Dq + h * HDq;
        const float* vp = kp + Dq;
        #pragma unroll
        for (int d4 = 0; d4 < 16; d4++) {
            float4 kv = ((const float4*)kp)[d4];
            Ks[tid][d4 * 4 + 0] = kv.x; Ks[tid][d4 * 4 + 1] = kv.y;
            Ks[tid][d4 * 4 + 2] = kv.z; Ks[tid][d4 * 4 + 3] = kv.w;
            float4 vv = ((const float4*)vp)[d4];
            Vs[tid][d4 * 4 + 0] = vv.x; Vs[tid][d4 * 4 + 1] = vv.y;
            Vs[tid][d4 * 4 + 2] = vv.z; Vs[tid][d4 * 4 + 3] = vv.w;
        }
        __syncthreads();

        int kbase = kt * 64;
        #pragma unroll 1
        for (int c = 0; c < 64; c += 16) {
            float s[16];
            #pragma unroll
            for (int j = 0; j < 16; j++) {
                float dot = 0.f;
                #pragma unroll
                for (int d = 0; d < 64; d++)
                    dot = fmaf(qreg[d], Ks[c + j][d], dot);
                int kpos = kbase + c + j;
                s[j] = (kpos <= qrow) ? dot * 0.125f : -1e30f;
            }
            float mt = m;
            #pragma unroll
            for (int j = 0; j < 16; j++) mt = fmaxf(mt, s[j]);
            if (mt > m) {
                float sc = expf(m - mt);
                l *= sc;
                #pragma unroll
                for (int d = 0; d < 64; d++) acc[d] *= sc;
                m = mt;
            }
            #pragma unroll
            for (int j = 0; j < 16; j++) {
                float p = expf(s[j] - m);
                l += p;
                #pragma unroll
                for (int d = 0; d < 64; d++)
                    acc[d] = fmaf(p, Vs[c + j][d], acc[d]);
            }
        }
        __syncthreads();
    }

    float inv_l = 1.0f / l;
    float* op = out + ((size_t)(b * Sq + qrow)) * Dq + h * HDq;
    #pragma unroll
    for (int d = 0; d < 64; d++) op[d] = acc[d] * inv_l;
}

// ---------------- layernorm (row = 768) ---------------------------------------
__global__ void __launch_bounds__(256)
layernorm_kernel(const float* __restrict__ in, const float* __restrict__ g,
                 const float* __restrict__ b, float* __restrict__ out) {
    int row = blockIdx.x;
    const float* x = in + (size_t)row * Dq;
    __shared__ float sx[Dq];
    __shared__ float red[256];
    int tid = threadIdx.x;

    float s = 0.f;
    for (int i = tid; i < Dq; i += 256) { float v = x[i]; sx[i] = v; s += v; }
    red[tid] = s; __syncthreads();
    for (int o = 128; o > 0; o >>= 1) { if (tid < o) red[tid] += red[tid + o]; __syncthreads(); }
    float mean = red[0] / (float)Dq;
    __syncthreads();

    float s2 = 0.f;
    for (int i = tid; i < Dq; i += 256) { float d = sx[i] - mean; s2 += d * d; }
    red[tid] = s2; __syncthreads();
    for (int o = 128; o > 0; o >>= 1) { if (tid < o) red[tid] += red[tid + o]; __syncthreads(); }
    float rstd = rsqrtf(red[0] / (float)Dq + 1e-5f);

    float* o = out + (size_t)row * Dq;
    for (int i = tid; i < Dq; i += 256)
        o[i] = (sx[i] - mean) * rstd * g[i] + b[i];
}

// ---------------- launch ------------------------------------------------------
extern "C" void kernel_launch(void* const* d_in, const int* in_sizes, int n_in,
                              void* d_out, int out_size) {
    (void)in_sizes; (void)n_in; (void)out_size;
    const int*   inputs = (const int*)  d_in[0];
    const float* emb    = (const float*)d_in[1];
    const float* W_qkv  = (const float*)d_in[2];
    const float* b_qkv  = (const float*)d_in[3];
    const float* W_o    = (const float*)d_in[4];
    const float* b_o    = (const float*)d_in[5];
    const float* ln1_g  = (const float*)d_in[6];
    const float* ln1_b  = (const float*)d_in[7];
    const float* W_ff1  = (const float*)d_in[8];
    const float* b_ff1  = (const float*)d_in[9];
    const float* W_ff2  = (const float*)d_in[10];
    const float* b_ff2  = (const float*)d_in[11];
    const float* ln2_g  = (const float*)d_in[12];
    const float* ln2_b  = (const float*)d_in[13];
    const float* W_out  = (const float*)d_in[14];
    const float* b_out  = (const float*)d_in[15];
    float* out = (float*)d_out;

    float *x, *qkv, *attn, *mha, *h1, *ff, *res2, *h2, *weff;
    cudaGetSymbolAddress((void**)&x,    g_x);
    cudaGetSymbolAddress((void**)&qkv,  g_qkv);
    cudaGetSymbolAddress((void**)&attn, g_attn);
    cudaGetSymbolAddress((void**)&mha,  g_mha);
    cudaGetSymbolAddress((void**)&h1,   g_h1);
    cudaGetSymbolAddress((void**)&ff,   g_ff);
    cudaGetSymbolAddress((void**)&res2, g_res2);
    cudaGetSymbolAddress((void**)&h2,   g_h2);
    cudaGetSymbolAddress((void**)&weff, g_weff);

    // 1) x = emb[inputs] + pos
    embed_pos_kernel<<<Mq, 256>>>(inputs, emb, x);

    // 2) W_eff = sum_h W_o blocks
    weff_kernel<<<(Dq * Dq + 255) / 256, 256>>>(W_o, weff);

    // 3) qkv = x @ W_qkv + b_qkv           [4096, 2304]
    sgemm_kernel<<<dim3(3 * Dq / 128, Mq / 128), 256>>>(
        x, W_qkv, b_qkv, nullptr, qkv, Mq, 3 * Dq, Dq, 0);

    // 4) flash attention -> attn           [4096, 768]
    attn_kernel<<<dim3(Sq / 64, Bq * Hq), 64>>>(qkv, attn);

    // 5) mha = attn @ W_eff + b_o + x
    sgemm_kernel<<<dim3(Dq / 128, Mq / 128), 256>>>(
        attn, weff, b_o, x, mha, Mq, Dq, Dq, 0);

    // 6) h1 = LN1(mha)
    layernorm_kernel<<<Mq, 256>>>(mha, ln1_g, ln1_b, h1);

    // 7) ff = relu(h1 @ W_ff1 + b_ff1)     [4096, 3072]
    sgemm_kernel<<<dim3(Fq / 128, Mq / 128), 256>>>(
        h1, W_ff1, b_ff1, nullptr, ff, Mq, Fq, Dq, 1);

    // 8) res2 = ff @ W_ff2 + b_ff2 + h1
    sgemm_kernel<<<dim3(Dq / 128, Mq / 128), 256>>>(
        ff, W_ff2, b_ff2, h1, res2, Mq, Dq, Fq, 0);

    // 9) h2 = LN2(res2)
    layernorm_kernel<<<Mq, 256>>>(res2, ln2_g, ln2_b, h2);

    // 10) logits = h2 @ W_out + b_out      [4096, 50257]
    sgemm_kernel<<<dim3((Vq + 127) / 128, Mq / 128), 256>>>(
        h2, W_out, b_out, nullptr, out, Mq, Vq, Dq, 0);
}